// round 1
// baseline (speedup 1.0000x reference)
#include <cuda_runtime.h>

// Param column order:
// 0 BW, 1 KMAX, 2 B, 3 D, 4 KMIN, 5 KABS, 6 F, 7 KP1, 8 KP2, 9 KP3,
// 10 FSNC, 11 KE1, 12 KE2, 13 K1, 14 K2, 15 VM0, 16 VMX, 17 KM0, 18 M1,
// 19 M2, 20 M4, 21 KA1, 22 KA2, 23 VI, 24 P2U, 25 IB, 26 KI, 27 M30,
// 28 KD, 29 KSC

__global__ __launch_bounds__(256)
void t1d_kernel(const float* __restrict__ x,
                const float* __restrict__ params,
                const float* __restrict__ action_ins,
                const float* __restrict__ action_CHO,
                const float* __restrict__ last_Qsto,
                const float* __restrict__ last_foodtaken,
                float* __restrict__ out,
                int n)
{
    int i = blockIdx.x * blockDim.x + threadIdx.x;
    if (i >= n) return;

    // ---- load 13 states ----
    const float* xr = x + (size_t)i * 13;
    float xs0 = xr[0],  xs1 = xr[1],  xs2 = xr[2],  xs3 = xr[3];
    float xs4 = xr[4],  xs5 = xr[5],  xs6 = xr[6],  xs7 = xr[7];
    float xs8 = xr[8],  xs9 = xr[9],  xs10 = xr[10], xs11 = xr[11];
    float xs12 = xr[12];

    // ---- load 30 params ----
    const float* pp = params + (size_t)i * 30;
    float BW   = pp[0],  KMAX = pp[1],  B    = pp[2],  D    = pp[3];
    float KMIN = pp[4],  KABS = pp[5],  F    = pp[6],  KP1  = pp[7];
    float KP2  = pp[8],  KP3  = pp[9],  FSNC = pp[10], KE1  = pp[11];
    float KE2  = pp[12], K1   = pp[13], K2   = pp[14], VM0  = pp[15];
    float VMX  = pp[16], KM0  = pp[17], M1   = pp[18], M2   = pp[19];
    float M4   = pp[20], KA1  = pp[21], KA2  = pp[22], VI   = pp[23];
    float P2U  = pp[24], IB   = pp[25], KI   = pp[26], M30  = pp[27];
    float KD   = pp[28], KSC  = pp[29];

    float ains = action_ins[i];
    float aCHO = action_CHO[i];
    float Dbar = last_Qsto[i] + last_foodtaken[i];

    // ---- dynamics ----
    float f_insulin = ains * 6000.0f / BW;
    float qsto = xs0 + xs1;

    float dx0 = -KMAX * xs0 + aCHO * 1000.0f;

    float denom = Dbar + 1e-7f;
    float aa = 2.5f / ((1.0f - B) * denom);
    float cc = 2.5f / (D * denom);
    float kgut_true = KMIN + (KMAX - KMIN) * 0.5f *
        (tanhf(aa * (qsto - B * Dbar)) - tanhf(cc * (qsto - D * Dbar)) + 2.0f);
    float kgut = (Dbar > 0.0f) ? kgut_true : KMAX;

    float dx1 = KMAX * xs0 - xs1 * kgut;
    float dx2 = kgut * xs1 - KABS * xs2;

    float Rat  = F * KABS * xs2 / BW;
    float EGPt = KP1 - KP2 * xs3 - KP3 * xs8;
    float Et   = (xs3 > KE2) ? KE1 * (xs3 - KE2) : 0.0f;
    float dx3  = fmaxf(EGPt, 0.0f) + Rat - FSNC - Et - K1 * xs3 + K2 * xs4;
    dx3 = (xs3 >= 0.0f) ? dx3 : 0.0f;

    float Vmt  = VM0 + VMX * xs6;
    float Uidt = Vmt * xs4 / (KM0 + xs4);
    float dx4  = -Uidt + K1 * xs3 - K2 * xs4;
    dx4 = (xs4 >= 0.0f) ? dx4 : 0.0f;

    float dx5 = -(M2 + M4) * xs5 + M1 * xs9 + KA1 * xs10 + KA2 * xs11;
    float It  = xs5 / VI;
    dx5 = (xs5 >= 0.0f) ? dx5 : 0.0f;

    float dx6 = -P2U * xs6 + P2U * (It - IB);
    float dx7 = -KI * (xs7 - It);
    float dx8 = -KI * (xs8 - xs7);

    float dx9 = -(M1 + M30) * xs9 + M2 * xs5;
    dx9 = (xs9 >= 0.0f) ? dx9 : 0.0f;

    float dx10 = f_insulin - (KA1 + KD) * xs10;
    dx10 = (xs10 >= 0.0f) ? dx10 : 0.0f;

    float dx11 = KD * xs10 - KA2 * xs11;
    dx11 = (xs11 >= 0.0f) ? dx11 : 0.0f;

    float dx12 = -KSC * xs12 + KSC * xs3;
    dx12 = (xs12 >= 0.0f) ? dx12 : 0.0f;

    // ---- store ----
    float* o = out + (size_t)i * 13;
    o[0]  = dx0;  o[1]  = dx1;  o[2]  = dx2;  o[3]  = dx3;
    o[4]  = dx4;  o[5]  = dx5;  o[6]  = dx6;  o[7]  = dx7;
    o[8]  = dx8;  o[9]  = dx9;  o[10] = dx10; o[11] = dx11;
    o[12] = dx12;
}

extern "C" void kernel_launch(void* const* d_in, const int* in_sizes, int n_in,
                              void* d_out, int out_size)
{
    const float* x    = (const float*)d_in[0];
    const float* prm  = (const float*)d_in[1];
    const float* ains = (const float*)d_in[2];
    const float* acho = (const float*)d_in[3];
    const float* lq   = (const float*)d_in[4];
    const float* lf   = (const float*)d_in[5];
    float* out = (float*)d_out;

    int n = in_sizes[0] / 13;  // x is (N,13)
    int threads = 256;
    int blocks = (n + threads - 1) / threads;
    t1d_kernel<<<blocks, threads>>>(x, prm, ains, acho, lq, lf, out, n);
}

// round 2
// speedup vs baseline: 2.0831x; 2.0831x over previous
#include <cuda_runtime.h>

#define TPB 256

// Param columns:
// 0 BW, 1 KMAX, 2 B, 3 D, 4 KMIN, 5 KABS, 6 F, 7 KP1, 8 KP2, 9 KP3,
// 10 FSNC, 11 KE1, 12 KE2, 13 K1, 14 K2, 15 VM0, 16 VMX, 17 KM0, 18 M1,
// 19 M2, 20 M4, 21 KA1, 22 KA2, 23 VI, 24 P2U, 25 IB, 26 KI, 27 M30,
// 28 KD, 29 KSC

__device__ __forceinline__ void compute_dx(
    const float xs[13], const float pv[30],
    float ains, float aCHO, float Dbar, float dx[13])
{
    float BW   = pv[0],  KMAX = pv[1],  B    = pv[2],  D    = pv[3];
    float KMIN = pv[4],  KABS = pv[5],  F    = pv[6],  KP1  = pv[7];
    float KP2  = pv[8],  KP3  = pv[9],  FSNC = pv[10], KE1  = pv[11];
    float KE2  = pv[12], K1   = pv[13], K2   = pv[14], VM0  = pv[15];
    float VMX  = pv[16], KM0  = pv[17], M1   = pv[18], M2   = pv[19];
    float M4   = pv[20], KA1  = pv[21], KA2  = pv[22], VI   = pv[23];
    float P2U  = pv[24], IB   = pv[25], KI   = pv[26], M30  = pv[27];
    float KD   = pv[28], KSC  = pv[29];

    float f_insulin = ains * 6000.0f / BW;
    float qsto = xs[0] + xs[1];

    dx[0] = -KMAX * xs[0] + aCHO * 1000.0f;

    float denom = Dbar + 1e-7f;
    float aa = 2.5f / ((1.0f - B) * denom);
    float cc = 2.5f / (D * denom);
    float kgut_true = KMIN + (KMAX - KMIN) * 0.5f *
        (tanhf(aa * (qsto - B * Dbar)) - tanhf(cc * (qsto - D * Dbar)) + 2.0f);
    float kgut = (Dbar > 0.0f) ? kgut_true : KMAX;

    dx[1] = KMAX * xs[0] - xs[1] * kgut;
    dx[2] = kgut * xs[1] - KABS * xs[2];

    float Rat  = F * KABS * xs[2] / BW;
    float EGPt = KP1 - KP2 * xs[3] - KP3 * xs[8];
    float Et   = (xs[3] > KE2) ? KE1 * (xs[3] - KE2) : 0.0f;
    float d3   = fmaxf(EGPt, 0.0f) + Rat - FSNC - Et - K1 * xs[3] + K2 * xs[4];
    dx[3] = (xs[3] >= 0.0f) ? d3 : 0.0f;

    float Vmt  = VM0 + VMX * xs[6];
    float Uidt = Vmt * xs[4] / (KM0 + xs[4]);
    float d4   = -Uidt + K1 * xs[3] - K2 * xs[4];
    dx[4] = (xs[4] >= 0.0f) ? d4 : 0.0f;

    float d5 = -(M2 + M4) * xs[5] + M1 * xs[9] + KA1 * xs[10] + KA2 * xs[11];
    float It = xs[5] / VI;
    dx[5] = (xs[5] >= 0.0f) ? d5 : 0.0f;

    dx[6] = -P2U * xs[6] + P2U * (It - IB);
    dx[7] = -KI * (xs[7] - It);
    dx[8] = -KI * (xs[8] - xs[7]);

    float d9 = -(M1 + M30) * xs[9] + M2 * xs[5];
    dx[9] = (xs[9] >= 0.0f) ? d9 : 0.0f;

    float d10 = f_insulin - (KA1 + KD) * xs[10];
    dx[10] = (xs[10] >= 0.0f) ? d10 : 0.0f;

    float d11 = KD * xs[10] - KA2 * xs[11];
    dx[11] = (xs[11] >= 0.0f) ? d11 : 0.0f;

    float d12 = -KSC * xs[12] + KSC * xs[3];
    dx[12] = (xs[12] >= 0.0f) ? d12 : 0.0f;
}

__global__ __launch_bounds__(TPB)
void t1d_kernel(const float* __restrict__ x,
                const float* __restrict__ params,
                const float* __restrict__ action_ins,
                const float* __restrict__ action_CHO,
                const float* __restrict__ last_Qsto,
                const float* __restrict__ last_foodtaken,
                float* __restrict__ out,
                int n)
{
    __shared__ float sx[TPB * 13];   // 13312 B; reused for outputs
    __shared__ float sp[TPB * 31];   // params padded 30 -> 31 floats/row

    const int tid  = threadIdx.x;
    const int base = blockIdx.x * TPB;
    const int i    = base + tid;

    const bool full = (base + TPB <= n);

    if (full) {
        // ---- stage x tile: 832 float4 coalesced loads ----
        const float4* __restrict__ xg = (const float4*)(x + (size_t)base * 13);
        float4* sx4 = (float4*)sx;
        #pragma unroll
        for (int j = 0; j < 3; j++) sx4[j * TPB + tid] = xg[j * TPB + tid];
        if (tid < (TPB * 13 / 4 - 3 * TPB)) sx4[3 * TPB + tid] = xg[3 * TPB + tid];

        // ---- stage params tile: 30 coalesced scalar passes, padded rows ----
        const float* __restrict__ pg = params + (size_t)base * 30;
        #pragma unroll
        for (int j = 0; j < 30; j++) {
            int e   = j * TPB + tid;
            int row = e / 30;
            int col = e - row * 30;
            sp[row * 31 + col] = pg[e];
        }
        __syncthreads();

        // ---- gather this thread's row (conflict-free strides 13 / 31) ----
        float xs[13], pv[30];
        #pragma unroll
        for (int k = 0; k < 13; k++) xs[k] = sx[tid * 13 + k];
        #pragma unroll
        for (int k = 0; k < 30; k++) pv[k] = sp[tid * 31 + k];

        float ains = action_ins[i];
        float aCHO = action_CHO[i];
        float Dbar = last_Qsto[i] + last_foodtaken[i];

        float dx[13];
        compute_dx(xs, pv, ains, aCHO, Dbar, dx);

        // ---- write own row back into sx (no cross-thread hazard) ----
        #pragma unroll
        for (int k = 0; k < 13; k++) sx[tid * 13 + k] = dx[k];
        __syncthreads();

        // ---- coalesced float4 stores ----
        float4* __restrict__ og = (float4*)(out + (size_t)base * 13);
        #pragma unroll
        for (int j = 0; j < 3; j++) og[j * TPB + tid] = sx4[j * TPB + tid];
        if (tid < (TPB * 13 / 4 - 3 * TPB)) og[3 * TPB + tid] = sx4[3 * TPB + tid];
    } else {
        // ---- tail block: scalar fallback ----
        if (i >= n) return;
        float xs[13], pv[30];
        const float* xr = x + (size_t)i * 13;
        #pragma unroll
        for (int k = 0; k < 13; k++) xs[k] = xr[k];
        const float* pp = params + (size_t)i * 30;
        #pragma unroll
        for (int k = 0; k < 30; k++) pv[k] = pp[k];

        float ains = action_ins[i];
        float aCHO = action_CHO[i];
        float Dbar = last_Qsto[i] + last_foodtaken[i];

        float dx[13];
        compute_dx(xs, pv, ains, aCHO, Dbar, dx);

        float* o = out + (size_t)i * 13;
        #pragma unroll
        for (int k = 0; k < 13; k++) o[k] = dx[k];
    }
}

extern "C" void kernel_launch(void* const* d_in, const int* in_sizes, int n_in,
                              void* d_out, int out_size)
{
    const float* x    = (const float*)d_in[0];
    const float* prm  = (const float*)d_in[1];
    const float* ains = (const float*)d_in[2];
    const float* acho = (const float*)d_in[3];
    const float* lq   = (const float*)d_in[4];
    const float* lf   = (const float*)d_in[5];
    float* out = (float*)d_out;

    int n = in_sizes[0] / 13;  // x is (N,13)
    int blocks = (n + TPB - 1) / TPB;
    t1d_kernel<<<blocks, TPB>>>(x, prm, ains, acho, lq, lf, out, n);
}